// round 3
// baseline (speedup 1.0000x reference)
#include <cuda_runtime.h>
#include <math.h>
#include <float.h>

#define BB 4
#define TT 1024
#define FF 1024
#define HH 16
#define DD 64
#define NR (BB*TT)        // 4096

// ---------------- scratch ----------------
__device__ float g_q[(size_t)NR * FF];
__device__ float g_k[(size_t)NR * FF];
__device__ float g_v[(size_t)NR * FF];
__device__ float g_x[(size_t)NR * FF];
__device__ int   g_mask_byte_mode;

// ---------------- helpers ----------------
__device__ __forceinline__ unsigned f2tf(float x) {
    unsigned r; asm("cvt.rna.tf32.f32 %0, %1;" : "=r"(r) : "f"(x)); return r;
}
__device__ __forceinline__ float f2tf_f(float x) {
    return __uint_as_float(f2tf(x));
}
__device__ __forceinline__ void mma8(float c[4], const unsigned a[4], const unsigned b[2]) {
    asm("mma.sync.aligned.m16n8k8.row.col.f32.tf32.tf32.f32 "
        "{%0,%1,%2,%3},{%4,%5,%6,%7},{%8,%9},{%0,%1,%2,%3};"
        : "+f"(c[0]), "+f"(c[1]), "+f"(c[2]), "+f"(c[3])
        : "r"(a[0]), "r"(a[1]), "r"(a[2]), "r"(a[3]), "r"(b[0]), "r"(b[1]));
}

// ---------------- mask dtype classifier ----------------
__global__ void detect_mask_kernel(const unsigned int* __restrict__ mask) {
    __shared__ int has_f, has_big;
    if (threadIdx.x == 0) { has_f = 0; has_big = 0; }
    __syncthreads();
    #pragma unroll
    for (int u = 0; u < 4; u++) {
        unsigned int w = mask[threadIdx.x * 4 + u];
        if (w == 0x3F800000u) atomicOr(&has_f, 1);
        else if (w > 1u)      atomicOr(&has_big, 1);
    }
    __syncthreads();
    if (threadIdx.x == 0)
        g_mask_byte_mode = (!has_f && has_big) ? 1 : 0;
}

// ---------------- QKV projections via tf32 mma, Q/K with hi+lo split ----------------
#define APAD 20
#define BPAD 136
__global__ __launch_bounds__(256) void proj_tf32_kernel(
    const float* __restrict__ q_in, const float* __restrict__ k_in,
    const float* __restrict__ v_in,
    const float* __restrict__ Wq, const float* __restrict__ bq,
    const float* __restrict__ Wk, const float* __restrict__ bk,
    const float* __restrict__ Wv, const float* __restrict__ bv)
{
    const float *A, *W, *bias; float *C; bool split;
    if (blockIdx.z == 0)      { A = q_in; W = Wq; bias = bq; C = g_q; split = true; }
    else if (blockIdx.z == 1) { A = k_in; W = Wk; bias = bk; C = g_k; split = true; }
    else                      { A = v_in; W = Wv; bias = bv; C = g_v; split = false; }

    __shared__ float Ah[128][APAD], Al[128][APAD];
    __shared__ float Bh[16][BPAD],  Bl[16][BPAD];

    int tid = threadIdx.x, lane = tid & 31, warp = tid >> 5;
    int wm = (warp >> 2) * 64, wn = (warp & 3) * 32;
    int bm = blockIdx.y * 128, bn = blockIdx.x * 128;

    float acc[4][4][4];
    #pragma unroll
    for (int i = 0; i < 4; i++)
        #pragma unroll
        for (int j = 0; j < 4; j++)
            #pragma unroll
            for (int r = 0; r < 4; r++) acc[i][j][r] = 0.f;

    for (int k0 = 0; k0 < FF; k0 += 16) {
        #pragma unroll
        for (int u = 0; u < 2; u++) {
            int s = tid + u * 256;
            int r  = s >> 2, c4 = (s & 3) * 4;
            float4 av = *(const float4*)(A + (size_t)(bm + r) * FF + k0 + c4);
            float4 hi, lo;
            hi.x = f2tf_f(av.x); lo.x = f2tf_f(av.x - hi.x);
            hi.y = f2tf_f(av.y); lo.y = f2tf_f(av.y - hi.y);
            hi.z = f2tf_f(av.z); lo.z = f2tf_f(av.z - hi.z);
            hi.w = f2tf_f(av.w); lo.w = f2tf_f(av.w - hi.w);
            *(float4*)&Ah[r][c4] = hi;
            *(float4*)&Al[r][c4] = lo;

            int rb = s >> 5, cb = (s & 31) * 4;
            float4 bv4 = *(const float4*)(W + (size_t)(k0 + rb) * FF + bn + cb);
            float4 bhi, blo;
            bhi.x = f2tf_f(bv4.x); blo.x = f2tf_f(bv4.x - bhi.x);
            bhi.y = f2tf_f(bv4.y); blo.y = f2tf_f(bv4.y - bhi.y);
            bhi.z = f2tf_f(bv4.z); blo.z = f2tf_f(bv4.z - bhi.z);
            bhi.w = f2tf_f(bv4.w); blo.w = f2tf_f(bv4.w - bhi.w);
            *(float4*)&Bh[rb][cb] = bhi;
            *(float4*)&Bl[rb][cb] = blo;
        }
        __syncthreads();
        #pragma unroll
        for (int ks = 0; ks < 16; ks += 8) {
            unsigned ah[4][4], bh[4][2];
            #pragma unroll
            for (int mt = 0; mt < 4; mt++) {
                int r = wm + mt * 16 + (lane >> 2);
                int k = ks + (lane & 3);
                ah[mt][0] = __float_as_uint(Ah[r][k]);
                ah[mt][1] = __float_as_uint(Ah[r + 8][k]);
                ah[mt][2] = __float_as_uint(Ah[r][k + 4]);
                ah[mt][3] = __float_as_uint(Ah[r + 8][k + 4]);
            }
            #pragma unroll
            for (int nt = 0; nt < 4; nt++) {
                int k = ks + (lane & 3);
                int n = wn + nt * 8 + (lane >> 2);
                bh[nt][0] = __float_as_uint(Bh[k][n]);
                bh[nt][1] = __float_as_uint(Bh[k + 4][n]);
            }
            #pragma unroll
            for (int mt = 0; mt < 4; mt++)
                #pragma unroll
                for (int nt = 0; nt < 4; nt++)
                    mma8(acc[mt][nt], ah[mt], bh[nt]);
            if (split) {
                unsigned al[4][4], bl[4][2];
                #pragma unroll
                for (int mt = 0; mt < 4; mt++) {
                    int r = wm + mt * 16 + (lane >> 2);
                    int k = ks + (lane & 3);
                    al[mt][0] = __float_as_uint(Al[r][k]);
                    al[mt][1] = __float_as_uint(Al[r + 8][k]);
                    al[mt][2] = __float_as_uint(Al[r][k + 4]);
                    al[mt][3] = __float_as_uint(Al[r + 8][k + 4]);
                }
                #pragma unroll
                for (int nt = 0; nt < 4; nt++) {
                    int k = ks + (lane & 3);
                    int n = wn + nt * 8 + (lane >> 2);
                    bl[nt][0] = __float_as_uint(Bl[k][n]);
                    bl[nt][1] = __float_as_uint(Bl[k + 4][n]);
                }
                #pragma unroll
                for (int mt = 0; mt < 4; mt++)
                    #pragma unroll
                    for (int nt = 0; nt < 4; nt++) {
                        mma8(acc[mt][nt], ah[mt], bl[nt]);
                        mma8(acc[mt][nt], al[mt], bh[nt]);
                    }
            }
        }
        __syncthreads();
    }
    #pragma unroll
    for (int mt = 0; mt < 4; mt++) {
        int r = bm + wm + mt * 16 + (lane >> 2);
        #pragma unroll
        for (int nt = 0; nt < 4; nt++) {
            int cc = bn + wn + nt * 8 + 2 * (lane & 3);
            float b0 = bias[cc], b1 = bias[cc + 1];
            float2 o0 = make_float2(acc[mt][nt][0] + b0, acc[mt][nt][1] + b1);
            float2 o1 = make_float2(acc[mt][nt][2] + b0, acc[mt][nt][3] + b1);
            *(float2*)(C + (size_t)r * FF + cc)       = o0;
            *(float2*)(C + (size_t)(r + 8) * FF + cc) = o1;
        }
    }
}

// ---------------- fused attention: full E row-block in smem, single write ----------------
#define ESTR 1040
#define KPAD 68
// smem floats: E 32*1040 + K 128*68 + Q 32*68 + lsum 32
#define ATT_SMEM ((32 * ESTR + 128 * KPAD + 32 * KPAD + 32) * 4)
__global__ __launch_bounds__(256) void attn_fused_kernel(
    float* __restrict__ attn, const unsigned int* __restrict__ mask,
    const float* __restrict__ qmask)
{
    extern __shared__ float sm[];
    float* E    = sm;
    float* Ks   = E + 32 * ESTR;           // also reused for V tiles
    float* Qs   = Ks + 128 * KPAD;
    float* lsum = Qs + 32 * KPAD;

    int tid = threadIdx.x, lane = tid & 31, warp = tid >> 5;
    int wr = warp >> 2, wc = warp & 3;     // 2 x 4 warp grid
    int hb = blockIdx.y, h = hb >> 2, b = hb & 3;
    int i0 = blockIdx.x * 32;
    int bytemode = g_mask_byte_mode;

    // load Q tile (32x64), single tf32
    #pragma unroll
    for (int u = 0; u < 2; u++) {
        int s = tid + u * 256;
        int r = s >> 4, c4 = (s & 15) * 4;
        float4 qv = *(const float4*)(g_q + (size_t)(b * TT + i0 + r) * FF + h * DD + c4);
        float4 hi;
        hi.x = f2tf_f(qv.x); hi.y = f2tf_f(qv.y);
        hi.z = f2tf_f(qv.z); hi.w = f2tf_f(qv.w);
        *(float4*)&Qs[r * KPAD + c4] = hi;
    }
    __syncthreads();

    // ---------- scores phase: 8 j-tiles of 128 ----------
    for (int j0 = 0; j0 < TT; j0 += 128) {
        #pragma unroll
        for (int u = 0; u < 8; u++) {
            int s = tid + u * 256;
            int r = s >> 4, c4 = (s & 15) * 4;
            float4 kv = *(const float4*)(g_k + (size_t)(b * TT + j0 + r) * FF + h * DD + c4);
            float4 hi;
            hi.x = f2tf_f(kv.x); hi.y = f2tf_f(kv.y);
            hi.z = f2tf_f(kv.z); hi.w = f2tf_f(kv.w);
            *(float4*)&Ks[r * KPAD + c4] = hi;
        }
        __syncthreads();

        float sacc[4][4];
        #pragma unroll
        for (int nt = 0; nt < 4; nt++)
            #pragma unroll
            for (int r = 0; r < 4; r++) sacc[nt][r] = 0.f;

        #pragma unroll
        for (int ks = 0; ks < 64; ks += 8) {
            unsigned ah[4], bh[4][2];
            int r = wr * 16 + (lane >> 2);
            int k = ks + (lane & 3);
            ah[0] = __float_as_uint(Qs[r * KPAD + k]);
            ah[1] = __float_as_uint(Qs[(r + 8) * KPAD + k]);
            ah[2] = __float_as_uint(Qs[r * KPAD + k + 4]);
            ah[3] = __float_as_uint(Qs[(r + 8) * KPAD + k + 4]);
            #pragma unroll
            for (int nt = 0; nt < 4; nt++) {
                int n = wc * 32 + nt * 8 + (lane >> 2);
                bh[nt][0] = __float_as_uint(Ks[n * KPAD + k]);
                bh[nt][1] = __float_as_uint(Ks[n * KPAD + k + 4]);
            }
            #pragma unroll
            for (int nt = 0; nt < 4; nt++)
                mma8(sacc[nt], ah, bh[nt]);
        }

        // mask + exp -> E (smem only)
        #pragma unroll
        for (int nt = 0; nt < 4; nt++) {
            int ri = wr * 16 + (lane >> 2);
            int cj = wc * 32 + nt * 8 + 2 * (lane & 3);
            size_t gi0 = ((size_t)hb * TT + i0 + ri) * TT + j0 + cj;
            size_t gi1 = gi0 + (size_t)8 * TT;
            unsigned m00, m01, m10, m11;
            if (bytemode) {
                const unsigned char* mb = (const unsigned char*)mask;
                m00 = mb[gi0]; m01 = mb[gi0 + 1];
                m10 = mb[gi1]; m11 = mb[gi1 + 1];
            } else {
                m00 = mask[gi0]; m01 = mask[gi0 + 1];
                m10 = mask[gi1]; m11 = mask[gi1 + 1];
            }
            E[ri * ESTR + j0 + cj]           = m00 ? 0.f : __expf(sacc[nt][0] * 0.125f);
            E[ri * ESTR + j0 + cj + 1]       = m01 ? 0.f : __expf(sacc[nt][1] * 0.125f);
            E[(ri + 8) * ESTR + j0 + cj]     = m10 ? 0.f : __expf(sacc[nt][2] * 0.125f);
            E[(ri + 8) * ESTR + j0 + cj + 1] = m11 ? 0.f : __expf(sacc[nt][3] * 0.125f);
        }
        __syncthreads();
    }

    // ---------- row sums ----------
    {
        int rr = tid >> 3, seg = (tid & 7) * 128;
        float p = 0.f;
        #pragma unroll
        for (int t = 0; t < 128; t += 4) {
            float4 e4 = *(const float4*)&E[rr * ESTR + seg + t];
            p += (e4.x + e4.y) + (e4.z + e4.w);
        }
        p += __shfl_xor_sync(0xFFFFFFFFu, p, 1);
        p += __shfl_xor_sync(0xFFFFFFFFu, p, 2);
        p += __shfl_xor_sync(0xFFFFFFFFu, p, 4);
        if ((tid & 7) == 0) lsum[rr] = p;
    }
    __syncthreads();

    // ---------- write normalized attn (single write) ----------
    #pragma unroll
    for (int u = 0; u < 32; u++) {
        int s = tid + u * 256;
        int r = s >> 8, c4 = (s & 255) * 4;
        float sc = qmask[b * TT + i0 + r] / lsum[r];
        float4 e4 = *(const float4*)&E[r * ESTR + c4];
        e4.x *= sc; e4.y *= sc; e4.z *= sc; e4.w *= sc;
        *(float4*)(attn + ((size_t)hb * TT + i0 + r) * TT + c4) = e4;
    }

    // ---------- X = E @ V ----------
    float X[2][4];
    #pragma unroll
    for (int nt = 0; nt < 2; nt++)
        #pragma unroll
        for (int r = 0; r < 4; r++) X[nt][r] = 0.f;

    for (int j0 = 0; j0 < TT; j0 += 64) {
        __syncthreads();
        #pragma unroll
        for (int u = 0; u < 4; u++) {
            int s = tid + u * 256;
            int r = s >> 4, c4 = (s & 15) * 4;
            float4 vv = *(const float4*)(g_v + (size_t)(b * TT + j0 + r) * FF + h * DD + c4);
            float4 hi;
            hi.x = f2tf_f(vv.x); hi.y = f2tf_f(vv.y);
            hi.z = f2tf_f(vv.z); hi.w = f2tf_f(vv.w);
            *(float4*)&Ks[r * KPAD + c4] = hi;
        }
        __syncthreads();
        #pragma unroll
        for (int ks = 0; ks < 64; ks += 8) {
            unsigned ae[4], bv[2][2];
            int r = wr * 16 + (lane >> 2);
            int kk = j0 + ks + (lane & 3);
            ae[0] = f2tf(E[r * ESTR + kk]);
            ae[1] = f2tf(E[(r + 8) * ESTR + kk]);
            ae[2] = f2tf(E[r * ESTR + kk + 4]);
            ae[3] = f2tf(E[(r + 8) * ESTR + kk + 4]);
            #pragma unroll
            for (int nt = 0; nt < 2; nt++) {
                int n = wc * 16 + nt * 8 + (lane >> 2);
                int k = ks + (lane & 3);
                bv[nt][0] = __float_as_uint(Ks[k * KPAD + n]);
                bv[nt][1] = __float_as_uint(Ks[(k + 4) * KPAD + n]);
            }
            #pragma unroll
            for (int nt = 0; nt < 2; nt++)
                mma8(X[nt], ae, bv[nt]);
        }
    }

    // epilogue: x = X * qmask / l
    {
        int ri = wr * 16 + (lane >> 2);
        float sc0 = qmask[b * TT + i0 + ri]     / lsum[ri];
        float sc1 = qmask[b * TT + i0 + ri + 8] / lsum[ri + 8];
        #pragma unroll
        for (int nt = 0; nt < 2; nt++) {
            int d = wc * 16 + nt * 8 + 2 * (lane & 3);
            float2 o0 = make_float2(X[nt][0] * sc0, X[nt][1] * sc0);
            float2 o1 = make_float2(X[nt][2] * sc1, X[nt][3] * sc1);
            *(float2*)(g_x + (size_t)(b * TT + i0 + ri) * FF + h * DD + d)     = o0;
            *(float2*)(g_x + (size_t)(b * TT + i0 + ri + 8) * FF + h * DD + d) = o1;
        }
    }
}

// ---------------- final: out = concat(x, query) @ Wf + bf + query (single tf32) ----------------
__global__ __launch_bounds__(256) void final_tf32_kernel(
    const float* __restrict__ query, const float* __restrict__ Wf,
    const float* __restrict__ bf, float* __restrict__ out)
{
    __shared__ float Ah[128][APAD];
    __shared__ float Bh[16][BPAD];

    const int K = 2 * FF;
    int tid = threadIdx.x, lane = tid & 31, warp = tid >> 5;
    int wm = (warp >> 2) * 64, wn = (warp & 3) * 32;
    int bm = blockIdx.y * 128, bn = blockIdx.x * 128;

    float acc[4][4][4];
    #pragma unroll
    for (int i = 0; i < 4; i++)
        #pragma unroll
        for (int j = 0; j < 4; j++)
            #pragma unroll
            for (int r = 0; r < 4; r++) acc[i][j][r] = 0.f;

    for (int k0 = 0; k0 < K; k0 += 16) {
        #pragma unroll
        for (int u = 0; u < 2; u++) {
            int s = tid + u * 256;
            int r = s >> 2, c4 = (s & 3) * 4;
            int col = k0 + c4;
            const float* src = (col < FF)
                ? (g_x + (size_t)(bm + r) * FF + col)
                : (query + (size_t)(bm + r) * FF + (col - FF));
            float4 av = *(const float4*)src;
            float4 hi;
            hi.x = f2tf_f(av.x); hi.y = f2tf_f(av.y);
            hi.z = f2tf_f(av.z); hi.w = f2tf_f(av.w);
            *(float4*)&Ah[r][c4] = hi;

            int rb = s >> 5, cb = (s & 31) * 4;
            float4 bv4 = *(const float4*)(Wf + (size_t)(k0 + rb) * FF + bn + cb);
            float4 bhi;
            bhi.x = f2tf_f(bv4.x); bhi.y = f2tf_f(bv4.y);
            bhi.z = f2tf_f(bv4.z); bhi.w = f2tf_f(bv4.w);
            *(float4*)&Bh[rb][cb] = bhi;
        }
        __syncthreads();
        #pragma unroll
        for (int ks = 0; ks < 16; ks += 8) {
            unsigned ah[4][4], bh[4][2];
            #pragma unroll
            for (int mt = 0; mt < 4; mt++) {
                int r = wm + mt * 16 + (lane >> 2);
                int k = ks + (lane & 3);
                ah[mt][0] = __float_as_uint(Ah[r][k]);
                ah[mt][1] = __float_as_uint(Ah[r + 8][k]);
                ah[mt][2] = __float_as_uint(Ah[r][k + 4]);
                ah[mt][3] = __float_as_uint(Ah[r + 8][k + 4]);
            }
            #pragma unroll
            for (int nt = 0; nt < 4; nt++) {
                int k = ks + (lane & 3);
                int n = wn + nt * 8 + (lane >> 2);
                bh[nt][0] = __float_as_uint(Bh[k][n]);
                bh[nt][1] = __float_as_uint(Bh[k + 4][n]);
            }
            #pragma unroll
            for (int mt = 0; mt < 4; mt++)
                #pragma unroll
                for (int nt = 0; nt < 4; nt++)
                    mma8(acc[mt][nt], ah[mt], bh[nt]);
        }
        __syncthreads();
    }
    #pragma unroll
    for (int mt = 0; mt < 4; mt++) {
        int r = bm + wm + mt * 16 + (lane >> 2);
        #pragma unroll
        for (int nt = 0; nt < 4; nt++) {
            int cc = bn + wn + nt * 8 + 2 * (lane & 3);
            float b0 = bf[cc], b1 = bf[cc + 1];
            const float* q0 = query + (size_t)r * FF + cc;
            const float* q1 = query + (size_t)(r + 8) * FF + cc;
            float2 o0 = make_float2(acc[mt][nt][0] + b0 + q0[0],
                                    acc[mt][nt][1] + b1 + q0[1]);
            float2 o1 = make_float2(acc[mt][nt][2] + b0 + q1[0],
                                    acc[mt][nt][3] + b1 + q1[1]);
            *(float2*)(out + (size_t)r * FF + cc)       = o0;
            *(float2*)(out + (size_t)(r + 8) * FF + cc) = o1;
        }
    }
}

// ---------------- launch ----------------
extern "C" void kernel_launch(void* const* d_in, const int* in_sizes, int n_in,
                              void* d_out, int out_size)
{
    const float* query = (const float*)d_in[0];
    const float* key   = (const float*)d_in[1];
    const float* value = (const float*)d_in[2];
    const unsigned int* mask = (const unsigned int*)d_in[3];
    const float* qmask = (const float*)d_in[4];
    const float* Wq = (const float*)d_in[5];
    const float* bq = (const float*)d_in[6];
    const float* Wk = (const float*)d_in[7];
    const float* bk = (const float*)d_in[8];
    const float* Wv = (const float*)d_in[9];
    const float* bv = (const float*)d_in[10];
    const float* Wf = (const float*)d_in[11];
    const float* bf = (const float*)d_in[12];

    float* out  = (float*)d_out;
    float* attn = out + (size_t)NR * FF;

    cudaFuncSetAttribute(attn_fused_kernel,
                         cudaFuncAttributeMaxDynamicSharedMemorySize, ATT_SMEM);

    detect_mask_kernel<<<1, 256>>>(mask);
    proj_tf32_kernel<<<dim3(8, 32, 3), 256>>>(query, key, value, Wq, bq, Wk, bk, Wv, bv);
    attn_fused_kernel<<<dim3(32, 64), 256, ATT_SMEM>>>(attn, mask, qmask);
    final_tf32_kernel<<<dim3(8, 32), 256>>>(query, Wf, bf, out);
}

// round 4
// speedup vs baseline: 1.4429x; 1.4429x over previous
#include <cuda_runtime.h>
#include <math.h>
#include <float.h>

#define BB 4
#define TT 1024
#define FF 1024
#define HH 16
#define DD 64
#define NR (BB*TT)        // 4096

// ---------------- scratch ----------------
__device__ float g_q[(size_t)NR * FF];
__device__ float g_k[(size_t)NR * FF];
__device__ float g_v[(size_t)NR * FF];
__device__ float g_x[(size_t)NR * FF];
__device__ float g_rowscale[HH * BB * TT];
__device__ int   g_mask_byte_mode;

// ---------------- helpers ----------------
__device__ __forceinline__ unsigned f2tf(float x) {
    unsigned r; asm("cvt.rna.tf32.f32 %0, %1;" : "=r"(r) : "f"(x)); return r;
}
__device__ __forceinline__ float f2tf_f(float x) {
    return __uint_as_float(f2tf(x));
}
__device__ __forceinline__ void mma8(float c[4], const unsigned a[4], const unsigned b[2]) {
    asm("mma.sync.aligned.m16n8k8.row.col.f32.tf32.tf32.f32 "
        "{%0,%1,%2,%3},{%4,%5,%6,%7},{%8,%9},{%0,%1,%2,%3};"
        : "+f"(c[0]), "+f"(c[1]), "+f"(c[2]), "+f"(c[3])
        : "r"(a[0]), "r"(a[1]), "r"(a[2]), "r"(a[3]), "r"(b[0]), "r"(b[1]));
}

// ---------------- mask dtype classifier ----------------
__global__ void detect_mask_kernel(const unsigned int* __restrict__ mask) {
    __shared__ int has_f, has_big;
    if (threadIdx.x == 0) { has_f = 0; has_big = 0; }
    __syncthreads();
    #pragma unroll
    for (int u = 0; u < 4; u++) {
        unsigned int w = mask[threadIdx.x * 4 + u];
        if (w == 0x3F800000u) atomicOr(&has_f, 1);
        else if (w > 1u)      atomicOr(&has_big, 1);
    }
    __syncthreads();
    if (threadIdx.x == 0)
        g_mask_byte_mode = (!has_f && has_big) ? 1 : 0;
}

// ---------------- QKV projections via tf32 mma; Q/K: 2-pass (A split, B single) ----------------
#define APAD 20
#define BPAD 136
__global__ __launch_bounds__(256) void proj_tf32_kernel(
    const float* __restrict__ q_in, const float* __restrict__ k_in,
    const float* __restrict__ v_in,
    const float* __restrict__ Wq, const float* __restrict__ bq,
    const float* __restrict__ Wk, const float* __restrict__ bk,
    const float* __restrict__ Wv, const float* __restrict__ bv)
{
    const float *A, *W, *bias; float *C; bool split;
    if (blockIdx.z == 0)      { A = q_in; W = Wq; bias = bq; C = g_q; split = true; }
    else if (blockIdx.z == 1) { A = k_in; W = Wk; bias = bk; C = g_k; split = true; }
    else                      { A = v_in; W = Wv; bias = bv; C = g_v; split = false; }

    __shared__ float Ah[128][APAD], Al[128][APAD];
    __shared__ float Bh[16][BPAD];

    int tid = threadIdx.x, lane = tid & 31, warp = tid >> 5;
    int wm = (warp >> 2) * 64, wn = (warp & 3) * 32;
    int bm = blockIdx.y * 128, bn = blockIdx.x * 128;

    float acc[4][4][4];
    #pragma unroll
    for (int i = 0; i < 4; i++)
        #pragma unroll
        for (int j = 0; j < 4; j++)
            #pragma unroll
            for (int r = 0; r < 4; r++) acc[i][j][r] = 0.f;

    for (int k0 = 0; k0 < FF; k0 += 16) {
        #pragma unroll
        for (int u = 0; u < 2; u++) {
            int s = tid + u * 256;
            int r  = s >> 2, c4 = (s & 3) * 4;
            float4 av = *(const float4*)(A + (size_t)(bm + r) * FF + k0 + c4);
            float4 hi, lo;
            hi.x = f2tf_f(av.x); lo.x = f2tf_f(av.x - hi.x);
            hi.y = f2tf_f(av.y); lo.y = f2tf_f(av.y - hi.y);
            hi.z = f2tf_f(av.z); lo.z = f2tf_f(av.z - hi.z);
            hi.w = f2tf_f(av.w); lo.w = f2tf_f(av.w - hi.w);
            *(float4*)&Ah[r][c4] = hi;
            *(float4*)&Al[r][c4] = lo;

            int rb = s >> 5, cb = (s & 31) * 4;
            float4 bv4 = *(const float4*)(W + (size_t)(k0 + rb) * FF + bn + cb);
            float4 bhi;
            bhi.x = f2tf_f(bv4.x); bhi.y = f2tf_f(bv4.y);
            bhi.z = f2tf_f(bv4.z); bhi.w = f2tf_f(bv4.w);
            *(float4*)&Bh[rb][cb] = bhi;
        }
        __syncthreads();
        #pragma unroll
        for (int ks = 0; ks < 16; ks += 8) {
            unsigned ah[4][4], bh[4][2];
            #pragma unroll
            for (int mt = 0; mt < 4; mt++) {
                int r = wm + mt * 16 + (lane >> 2);
                int k = ks + (lane & 3);
                ah[mt][0] = __float_as_uint(Ah[r][k]);
                ah[mt][1] = __float_as_uint(Ah[r + 8][k]);
                ah[mt][2] = __float_as_uint(Ah[r][k + 4]);
                ah[mt][3] = __float_as_uint(Ah[r + 8][k + 4]);
            }
            #pragma unroll
            for (int nt = 0; nt < 4; nt++) {
                int k = ks + (lane & 3);
                int n = wn + nt * 8 + (lane >> 2);
                bh[nt][0] = __float_as_uint(Bh[k][n]);
                bh[nt][1] = __float_as_uint(Bh[k + 4][n]);
            }
            #pragma unroll
            for (int mt = 0; mt < 4; mt++)
                #pragma unroll
                for (int nt = 0; nt < 4; nt++)
                    mma8(acc[mt][nt], ah[mt], bh[nt]);
            if (split) {
                unsigned al[4][4];
                #pragma unroll
                for (int mt = 0; mt < 4; mt++) {
                    int r = wm + mt * 16 + (lane >> 2);
                    int k = ks + (lane & 3);
                    al[mt][0] = __float_as_uint(Al[r][k]);
                    al[mt][1] = __float_as_uint(Al[r + 8][k]);
                    al[mt][2] = __float_as_uint(Al[r][k + 4]);
                    al[mt][3] = __float_as_uint(Al[r + 8][k + 4]);
                }
                #pragma unroll
                for (int mt = 0; mt < 4; mt++)
                    #pragma unroll
                    for (int nt = 0; nt < 4; nt++)
                        mma8(acc[mt][nt], al[mt], bh[nt]);
            }
        }
        __syncthreads();
    }
    #pragma unroll
    for (int mt = 0; mt < 4; mt++) {
        int r = bm + wm + mt * 16 + (lane >> 2);
        #pragma unroll
        for (int nt = 0; nt < 4; nt++) {
            int cc = bn + wn + nt * 8 + 2 * (lane & 3);
            float b0 = bias[cc], b1 = bias[cc + 1];
            float2 o0 = make_float2(acc[mt][nt][0] + b0, acc[mt][nt][1] + b1);
            float2 o1 = make_float2(acc[mt][nt][2] + b0, acc[mt][nt][3] + b1);
            *(float2*)(C + (size_t)r * FF + cc)       = o0;
            *(float2*)(C + (size_t)(r + 8) * FF + cc) = o1;
        }
    }
}

// ---------------- fused attention (R2 design): S split tf32 + mask + exp + AV ----------------
#define EPAD 68
#define ATT_SMEM ((6 * 64 * EPAD + 64) * 4)
__global__ __launch_bounds__(256) void attn_fused_kernel(
    float* __restrict__ attn, const unsigned int* __restrict__ mask,
    const float* __restrict__ qmask)
{
    extern __shared__ float sm[];
    float* Qh   = sm;
    float* Ql   = Qh + 64 * EPAD;
    float* Kh   = Ql + 64 * EPAD;
    float* Kl   = Kh + 64 * EPAD;
    float* Vs   = Kl + 64 * EPAD;
    float* Es   = Vs + 64 * EPAD;
    float* lsum = Es + 64 * EPAD;

    int tid = threadIdx.x, lane = tid & 31, warp = tid >> 5;
    int hb = blockIdx.y, h = hb >> 2, b = hb & 3;
    int i0 = blockIdx.x * 64;
    int wm = (warp >> 2) * 32, wn = (warp & 3) * 16;
    int bytemode = g_mask_byte_mode;

    #pragma unroll
    for (int u = 0; u < 4; u++) {
        int s = tid + u * 256;
        int r = s >> 4, c4 = (s & 15) * 4;
        float4 qv = *(const float4*)(g_q + (size_t)(b * TT + i0 + r) * FF + h * DD + c4);
        float4 hi, lo;
        hi.x = f2tf_f(qv.x); lo.x = f2tf_f(qv.x - hi.x);
        hi.y = f2tf_f(qv.y); lo.y = f2tf_f(qv.y - hi.y);
        hi.z = f2tf_f(qv.z); lo.z = f2tf_f(qv.z - hi.z);
        hi.w = f2tf_f(qv.w); lo.w = f2tf_f(qv.w - hi.w);
        *(float4*)&Qh[r * EPAD + c4] = hi;
        *(float4*)&Ql[r * EPAD + c4] = lo;
    }
    if (tid < 64) lsum[tid] = 0.f;

    float X[2][2][4];
    #pragma unroll
    for (int i = 0; i < 2; i++)
        #pragma unroll
        for (int j = 0; j < 2; j++)
            #pragma unroll
            for (int r = 0; r < 4; r++) X[i][j][r] = 0.f;

    __syncthreads();

    for (int j0 = 0; j0 < TT; j0 += 64) {
        #pragma unroll
        for (int u = 0; u < 4; u++) {
            int s = tid + u * 256;
            int r = s >> 4, c4 = (s & 15) * 4;
            float4 kv = *(const float4*)(g_k + (size_t)(b * TT + j0 + r) * FF + h * DD + c4);
            float4 hi, lo;
            hi.x = f2tf_f(kv.x); lo.x = f2tf_f(kv.x - hi.x);
            hi.y = f2tf_f(kv.y); lo.y = f2tf_f(kv.y - hi.y);
            hi.z = f2tf_f(kv.z); lo.z = f2tf_f(kv.z - hi.z);
            hi.w = f2tf_f(kv.w); lo.w = f2tf_f(kv.w - hi.w);
            *(float4*)&Kh[r * EPAD + c4] = hi;
            *(float4*)&Kl[r * EPAD + c4] = lo;
            float4 vv = *(const float4*)(g_v + (size_t)(b * TT + j0 + r) * FF + h * DD + c4);
            float4 vh;
            vh.x = f2tf_f(vv.x); vh.y = f2tf_f(vv.y);
            vh.z = f2tf_f(vv.z); vh.w = f2tf_f(vv.w);
            *(float4*)&Vs[r * EPAD + c4] = vh;
        }
        __syncthreads();

        float sacc[2][2][4];
        #pragma unroll
        for (int i = 0; i < 2; i++)
            #pragma unroll
            for (int j = 0; j < 2; j++)
                #pragma unroll
                for (int r = 0; r < 4; r++) sacc[i][j][r] = 0.f;

        #pragma unroll
        for (int ks = 0; ks < 64; ks += 8) {
            unsigned ah[2][4], al[2][4], bh[2][2], bl[2][2];
            #pragma unroll
            for (int mt = 0; mt < 2; mt++) {
                int r = wm + mt * 16 + (lane >> 2);
                int k = ks + (lane & 3);
                ah[mt][0] = __float_as_uint(Qh[r * EPAD + k]);
                ah[mt][1] = __float_as_uint(Qh[(r + 8) * EPAD + k]);
                ah[mt][2] = __float_as_uint(Qh[r * EPAD + k + 4]);
                ah[mt][3] = __float_as_uint(Qh[(r + 8) * EPAD + k + 4]);
                al[mt][0] = __float_as_uint(Ql[r * EPAD + k]);
                al[mt][1] = __float_as_uint(Ql[(r + 8) * EPAD + k]);
                al[mt][2] = __float_as_uint(Ql[r * EPAD + k + 4]);
                al[mt][3] = __float_as_uint(Ql[(r + 8) * EPAD + k + 4]);
            }
            #pragma unroll
            for (int nt = 0; nt < 2; nt++) {
                int n = wn + nt * 8 + (lane >> 2);
                int k = ks + (lane & 3);
                bh[nt][0] = __float_as_uint(Kh[n * EPAD + k]);
                bh[nt][1] = __float_as_uint(Kh[n * EPAD + k + 4]);
                bl[nt][0] = __float_as_uint(Kl[n * EPAD + k]);
                bl[nt][1] = __float_as_uint(Kl[n * EPAD + k + 4]);
            }
            #pragma unroll
            for (int mt = 0; mt < 2; mt++)
                #pragma unroll
                for (int nt = 0; nt < 2; nt++) {
                    mma8(sacc[mt][nt], ah[mt], bh[nt]);
                    mma8(sacc[mt][nt], ah[mt], bl[nt]);
                    mma8(sacc[mt][nt], al[mt], bh[nt]);
                }
        }

        #pragma unroll
        for (int mt = 0; mt < 2; mt++) {
            #pragma unroll
            for (int nt = 0; nt < 2; nt++) {
                int ri = wm + mt * 16 + (lane >> 2);
                int cj = wn + nt * 8 + 2 * (lane & 3);
                size_t gi0 = ((size_t)hb * TT + i0 + ri) * TT + j0 + cj;
                size_t gi1 = gi0 + (size_t)8 * TT;
                unsigned m00, m01, m10, m11;
                if (bytemode) {
                    const unsigned char* mb = (const unsigned char*)mask;
                    m00 = mb[gi0]; m01 = mb[gi0 + 1];
                    m10 = mb[gi1]; m11 = mb[gi1 + 1];
                } else {
                    m00 = mask[gi0]; m01 = mask[gi0 + 1];
                    m10 = mask[gi1]; m11 = mask[gi1 + 1];
                }
                float e00 = m00 ? 0.f : __expf(sacc[mt][nt][0] * 0.125f);
                float e01 = m01 ? 0.f : __expf(sacc[mt][nt][1] * 0.125f);
                float e10 = m10 ? 0.f : __expf(sacc[mt][nt][2] * 0.125f);
                float e11 = m11 ? 0.f : __expf(sacc[mt][nt][3] * 0.125f);
                *(float2*)(attn + gi0) = make_float2(e00, e01);
                *(float2*)(attn + gi1) = make_float2(e10, e11);
                Es[ri * EPAD + cj]           = e00;
                Es[ri * EPAD + cj + 1]       = e01;
                Es[(ri + 8) * EPAD + cj]     = e10;
                Es[(ri + 8) * EPAD + cj + 1] = e11;
            }
        }
        __syncthreads();

        {
            int r = tid >> 2, seg = (tid & 3) * 16;
            float p = 0.f;
            #pragma unroll
            for (int t = 0; t < 16; t++) p += Es[r * EPAD + seg + t];
            p += __shfl_xor_sync(0xFFFFFFFFu, p, 1);
            p += __shfl_xor_sync(0xFFFFFFFFu, p, 2);
            if ((tid & 3) == 0) lsum[r] += p;
        }

        #pragma unroll
        for (int ks = 0; ks < 64; ks += 8) {
            unsigned ae[2][4], bv[2][2];
            #pragma unroll
            for (int mt = 0; mt < 2; mt++) {
                int r = wm + mt * 16 + (lane >> 2);
                int k = ks + (lane & 3);
                ae[mt][0] = f2tf(Es[r * EPAD + k]);
                ae[mt][1] = f2tf(Es[(r + 8) * EPAD + k]);
                ae[mt][2] = f2tf(Es[r * EPAD + k + 4]);
                ae[mt][3] = f2tf(Es[(r + 8) * EPAD + k + 4]);
            }
            #pragma unroll
            for (int nt = 0; nt < 2; nt++) {
                int n = wn + nt * 8 + (lane >> 2);
                int k = ks + (lane & 3);
                bv[nt][0] = __float_as_uint(Vs[k * EPAD + n]);
                bv[nt][1] = __float_as_uint(Vs[(k + 4) * EPAD + n]);
            }
            #pragma unroll
            for (int mt = 0; mt < 2; mt++)
                #pragma unroll
                for (int nt = 0; nt < 2; nt++)
                    mma8(X[mt][nt], ae[mt], bv[nt]);
        }
        __syncthreads();
    }

    #pragma unroll
    for (int mt = 0; mt < 2; mt++) {
        int ri = wm + mt * 16 + (lane >> 2);
        float sc0 = qmask[b * TT + i0 + ri]     / lsum[ri];
        float sc1 = qmask[b * TT + i0 + ri + 8] / lsum[ri + 8];
        #pragma unroll
        for (int nt = 0; nt < 2; nt++) {
            int d = wn + nt * 8 + 2 * (lane & 3);
            float2 o0 = make_float2(X[mt][nt][0] * sc0, X[mt][nt][1] * sc0);
            float2 o1 = make_float2(X[mt][nt][2] * sc1, X[mt][nt][3] * sc1);
            *(float2*)(g_x + (size_t)(b * TT + i0 + ri) * FF + h * DD + d)     = o0;
            *(float2*)(g_x + (size_t)(b * TT + i0 + ri + 8) * FF + h * DD + d) = o1;
        }
    }
    if (tid < 64)
        g_rowscale[hb * TT + i0 + tid] = qmask[b * TT + i0 + tid] / lsum[tid];
}

// ---------------- normalize attn in place ----------------
__global__ __launch_bounds__(256) void normalize_kernel(float* __restrict__ attn)
{
    int row = blockIdx.x;
    float s = g_rowscale[row];
    float4* p = (float4*)(attn + (size_t)row * TT) + threadIdx.x;
    float4 v = *p;
    v.x *= s; v.y *= s; v.z *= s; v.w *= s;
    *p = v;
}

// ---------------- final: out = concat(x, query) @ Wf + bf + query (single tf32) ----------------
__global__ __launch_bounds__(256) void final_tf32_kernel(
    const float* __restrict__ query, const float* __restrict__ Wf,
    const float* __restrict__ bf, float* __restrict__ out)
{
    __shared__ float Ah[128][APAD];
    __shared__ float Bh[16][BPAD];

    const int K = 2 * FF;
    int tid = threadIdx.x, lane = tid & 31, warp = tid >> 5;
    int wm = (warp >> 2) * 64, wn = (warp & 3) * 32;
    int bm = blockIdx.y * 128, bn = blockIdx.x * 128;

    float acc[4][4][4];
    #pragma unroll
    for (int i = 0; i < 4; i++)
        #pragma unroll
        for (int j = 0; j < 4; j++)
            #pragma unroll
            for (int r = 0; r < 4; r++) acc[i][j][r] = 0.f;

    for (int k0 = 0; k0 < K; k0 += 16) {
        #pragma unroll
        for (int u = 0; u < 2; u++) {
            int s = tid + u * 256;
            int r = s >> 2, c4 = (s & 3) * 4;
            int col = k0 + c4;
            const float* src = (col < FF)
                ? (g_x + (size_t)(bm + r) * FF + col)
                : (query + (size_t)(bm + r) * FF + (col - FF));
            float4 av = *(const float4*)src;
            float4 hi;
            hi.x = f2tf_f(av.x); hi.y = f2tf_f(av.y);
            hi.z = f2tf_f(av.z); hi.w = f2tf_f(av.w);
            *(float4*)&Ah[r][c4] = hi;

            int rb = s >> 5, cb = (s & 31) * 4;
            float4 bv4 = *(const float4*)(Wf + (size_t)(k0 + rb) * FF + bn + cb);
            float4 bhi;
            bhi.x = f2tf_f(bv4.x); bhi.y = f2tf_f(bv4.y);
            bhi.z = f2tf_f(bv4.z); bhi.w = f2tf_f(bv4.w);
            *(float4*)&Bh[rb][cb] = bhi;
        }
        __syncthreads();
        #pragma unroll
        for (int ks = 0; ks < 16; ks += 8) {
            unsigned ah[4][4], bh[4][2];
            #pragma unroll
            for (int mt = 0; mt < 4; mt++) {
                int r = wm + mt * 16 + (lane >> 2);
                int k = ks + (lane & 3);
                ah[mt][0] = __float_as_uint(Ah[r][k]);
                ah[mt][1] = __float_as_uint(Ah[r + 8][k]);
                ah[mt][2] = __float_as_uint(Ah[r][k + 4]);
                ah[mt][3] = __float_as_uint(Ah[r + 8][k + 4]);
            }
            #pragma unroll
            for (int nt = 0; nt < 4; nt++) {
                int k = ks + (lane & 3);
                int n = wn + nt * 8 + (lane >> 2);
                bh[nt][0] = __float_as_uint(Bh[k][n]);
                bh[nt][1] = __float_as_uint(Bh[k + 4][n]);
            }
            #pragma unroll
            for (int mt = 0; mt < 4; mt++)
                #pragma unroll
                for (int nt = 0; nt < 4; nt++)
                    mma8(acc[mt][nt], ah[mt], bh[nt]);
        }
        __syncthreads();
    }
    #pragma unroll
    for (int mt = 0; mt < 4; mt++) {
        int r = bm + wm + mt * 16 + (lane >> 2);
        #pragma unroll
        for (int nt = 0; nt < 4; nt++) {
            int cc = bn + wn + nt * 8 + 2 * (lane & 3);
            float b0 = bf[cc], b1 = bf[cc + 1];
            const float* q0 = query + (size_t)r * FF + cc;
            const float* q1 = query + (size_t)(r + 8) * FF + cc;
            float2 o0 = make_float2(acc[mt][nt][0] + b0 + q0[0],
                                    acc[mt][nt][1] + b1 + q0[1]);
            float2 o1 = make_float2(acc[mt][nt][2] + b0 + q1[0],
                                    acc[mt][nt][3] + b1 + q1[1]);
            *(float2*)(out + (size_t)r * FF + cc)       = o0;
            *(float2*)(out + (size_t)(r + 8) * FF + cc) = o1;
        }
    }
}

// ---------------- launch ----------------
extern "C" void kernel_launch(void* const* d_in, const int* in_sizes, int n_in,
                              void* d_out, int out_size)
{
    const float* query = (const float*)d_in[0];
    const float* key   = (const float*)d_in[1];
    const float* value = (const float*)d_in[2];
    const unsigned int* mask = (const unsigned int*)d_in[3];
    const float* qmask = (const float*)d_in[4];
    const float* Wq = (const float*)d_in[5];
    const float* bq = (const float*)d_in[6];
    const float* Wk = (const float*)d_in[7];
    const float* bk = (const float*)d_in[8];
    const float* Wv = (const float*)d_in[9];
    const float* bv = (const float*)d_in[10];
    const float* Wf = (const float*)d_in[11];
    const float* bf = (const float*)d_in[12];

    float* out  = (float*)d_out;
    float* attn = out + (size_t)NR * FF;

    cudaFuncSetAttribute(attn_fused_kernel,
                         cudaFuncAttributeMaxDynamicSharedMemorySize, ATT_SMEM);

    detect_mask_kernel<<<1, 256>>>(mask);
    proj_tf32_kernel<<<dim3(8, 32, 3), 256>>>(query, key, value, Wq, bq, Wk, bk, Wv, bv);
    attn_fused_kernel<<<dim3(16, 64), 256, ATT_SMEM>>>(attn, mask, qmask);
    normalize_kernel<<<dim3(HH * BB * TT), 256>>>(attn);
    final_tf32_kernel<<<dim3(8, 32), 256>>>(query, Wf, bf, out);
}